// round 1
// baseline (speedup 1.0000x reference)
#include <cuda_runtime.h>

#define Bb     2
#define CIN    32
#define COUT   64
#define KK     9
#define HH     256
#define WW     512
#define OH     256
#define OW     512
#define HWSZ   (HH*WW)        // 131072
#define OHW    (OH*OW)        // 131072
#define CK     (CIN*KK)       // 288

#define TPIX   32             // output pixels per block
#define NCOL   (2*TPIX)       // 64 gemm columns (pixels x batch)
#define SPAD   65             // padded S row stride
#define NTHR   512

// scratch: x transposed to [B, H*W, C]  (33.5 MB) and weight transposed to [ck][o]
__device__ __align__(16) float g_xt[(size_t)Bb*HWSZ*CIN];
__device__ __align__(16) float g_wt[CK*COUT];

// ---------------- transpose x: [B,C,HW] -> [B,HW,C] ----------------
__global__ void transpose_kernel(const float* __restrict__ x) {
    __shared__ float tile[32][33];
    int b   = blockIdx.y;
    int hw0 = blockIdx.x * 32;
    int tx  = threadIdx.x & 31;
    int ty  = threadIdx.x >> 5;        // 0..7
#pragma unroll
    for (int r = 0; r < 4; r++) {
        int c = r*8 + ty;
        tile[c][tx] = x[((size_t)b*CIN + c)*HWSZ + hw0 + tx];   // coalesced over hw
    }
    __syncthreads();
#pragma unroll
    for (int r = 0; r < 4; r++) {
        int hwi = r*8 + ty;
        g_xt[((size_t)b*HWSZ + hw0 + hwi)*CIN + tx] = tile[tx][hwi];  // coalesced over c
    }
}

// ---------------- weight transpose: W[o][c][k] -> Wt[k*32+c][o] ----------------
__global__ void wt_kernel(const float* __restrict__ w) {
    int i = blockIdx.x*256 + threadIdx.x;
    if (i < CK*COUT) {
        int ck = i >> 6, o = i & 63;
        int k = ck >> 5, c = ck & 31;
        g_wt[i] = w[(o*CIN + c)*KK + k];
    }
}

// ---------------- main: gather + gemm ----------------
__global__ void __launch_bounds__(NTHR, 1)
mapped_conv_kernel(const float* __restrict__ bias,
                   const float* __restrict__ smap,
                   float* __restrict__ out)
{
    extern __shared__ float sm[];
    float* sWt   = sm;                       // CK*64      = 18432 floats
    float* sS    = sWt  + CK*COUT;           // CK*SPAD    = 18720 floats
    float* sWgt  = sS   + CK*SPAD;           // 288*4      = 1152 floats
    int*   sIdx  = (int*)(sWgt + TPIX*KK*4); // 288*4 ints
    float* sBias = (float*)(sIdx + TPIX*KK*4); // 64

    const int tid  = threadIdx.x;
    const int pix0 = blockIdx.x * TPIX;

    // stage Wt + bias
    for (int i = tid; i < CK*COUT; i += NTHR) sWt[i] = g_wt[i];
    if (tid < COUT) sBias[tid] = bias[tid];

    // coords: one thread per (pixel,k) task; pk = p*9+k
    if (tid < TPIX*KK) {
        int p = tid / KK, k = tid - p*KK;
        int pix = pix0 + p;
        float sx = smap[(pix*KK + k)*2 + 0];
        float sy = smap[(pix*KK + k)*2 + 1];
        float bx = floorf(sx), by = floorf(sy);
        float fx = sx - bx, fy = sy - by;
        int x0 = (int)bx, y0 = (int)by;
        int x0c = min(max(x0,     0), WW-1);
        int x1c = min(max(x0 + 1, 0), WW-1);
        int y0c = min(max(y0,     0), HH-1);
        int y1c = min(max(y0 + 1, 0), HH-1);
        sIdx[tid*4+0] = y0c*WW + x0c;
        sIdx[tid*4+1] = y0c*WW + x1c;
        sIdx[tid*4+2] = y1c*WW + x0c;
        sIdx[tid*4+3] = y1c*WW + x1c;
        sWgt[tid*4+0] = (1.f-fx)*(1.f-fy);
        sWgt[tid*4+1] = fx*(1.f-fy);
        sWgt[tid*4+2] = (1.f-fx)*fy;
        sWgt[tid*4+3] = fx*fy;
    }
    __syncthreads();

    // ---- gather phase: tasks = 32pix * 9k * 2b * 8cquad = 4608 = 9 iters * 512 thr
    // task layout: cq = low 3 bits -> 8 lanes of one (pk,b) share one 128B line per tap
    const float4* xt4 = (const float4*)g_xt;  // float4 idx = (b*HW + spatial)*8 + cq
#pragma unroll 3
    for (int it = 0; it < 9; it++) {
        int task = it*NTHR + tid;
        int cq = task & 7;
        int b  = (task >> 3) & 1;
        int pk = task >> 4;              // p*9 + k
        int p  = pk / KK;
        int k  = pk - p*KK;
        int col = b*TPIX + p;

        float w0 = sWgt[pk*4+0], w1 = sWgt[pk*4+1];
        float w2 = sWgt[pk*4+2], w3 = sWgt[pk*4+3];
        size_t base = (size_t)b*HWSZ;
        float4 v0 = xt4[(base + sIdx[pk*4+0])*8 + cq];
        float4 v1 = xt4[(base + sIdx[pk*4+1])*8 + cq];
        float4 v2 = xt4[(base + sIdx[pk*4+2])*8 + cq];
        float4 v3 = xt4[(base + sIdx[pk*4+3])*8 + cq];

        float4 a;
        a.x = w0*v0.x + w1*v1.x + w2*v2.x + w3*v3.x;
        a.y = w0*v0.y + w1*v1.y + w2*v2.y + w3*v3.y;
        a.z = w0*v0.z + w1*v1.z + w2*v2.z + w3*v3.z;
        a.w = w0*v0.w + w1*v1.w + w2*v2.w + w3*v3.w;

        int ckb = k*CIN + cq*4;
        sS[(ckb+0)*SPAD + col] = a.x;
        sS[(ckb+1)*SPAD + col] = a.y;
        sS[(ckb+2)*SPAD + col] = a.z;
        sS[(ckb+3)*SPAD + col] = a.w;
    }
    __syncthreads();

    // ---- gemm phase: C[64 o x 64 col], thread tile 4o x 2col
    const int cg = tid & 31;         // column within half (also pixel index)
    const int og = tid >> 5;         // 0..15
    const int o0 = og * 4;
    float acc0[4] = {0.f,0.f,0.f,0.f};
    float acc1[4] = {0.f,0.f,0.f,0.f};
#pragma unroll 4
    for (int ck = 0; ck < CK; ck++) {
        float4 wv = *(const float4*)&sWt[ck*COUT + o0];   // warp-uniform -> broadcast
        float s0 = sS[ck*SPAD + cg];                      // b=0 column
        float s1 = sS[ck*SPAD + cg + 32];                 // b=1 column
        acc0[0] += wv.x*s0;  acc1[0] += wv.x*s1;
        acc0[1] += wv.y*s0;  acc1[1] += wv.y*s1;
        acc0[2] += wv.z*s0;  acc1[2] += wv.z*s1;
        acc0[3] += wv.w*s0;  acc1[3] += wv.w*s1;
    }

    // epilogue: out[b][o][pix], coalesced over cg
    int pix = pix0 + cg;
#pragma unroll
    for (int j = 0; j < 4; j++) {
        float bv = sBias[o0 + j];
        out[((size_t)(0*COUT + o0 + j))*OHW + pix] = acc0[j] + bv;
        out[((size_t)(1*COUT + o0 + j))*OHW + pix] = acc1[j] + bv;
    }
}

#define SMEM_BYTES ((CK*COUT + CK*SPAD + TPIX*KK*4 + COUT)*4 + TPIX*KK*4*4)

extern "C" void kernel_launch(void* const* d_in, const int* in_sizes, int n_in,
                              void* d_out, int out_size) {
    const float* x    = (const float*)d_in[0];
    const float* w    = (const float*)d_in[1];
    const float* bias = (const float*)d_in[2];
    const float* smap = (const float*)d_in[3];
    float* out = (float*)d_out;

    cudaFuncSetAttribute(mapped_conv_kernel,
                         cudaFuncAttributeMaxDynamicSharedMemorySize, SMEM_BYTES);

    transpose_kernel<<<dim3(HWSZ/32, Bb), 256>>>(x);
    wt_kernel<<<(CK*COUT + 255)/256, 256>>>(w);
    mapped_conv_kernel<<<OHW/TPIX, NTHR, SMEM_BYTES>>>(bias, smap, out);
}

// round 3
// speedup vs baseline: 1.2250x; 1.2250x over previous
#include <cuda_runtime.h>
#include <cstdint>

#define Bb     2
#define CIN    32
#define COUT   64
#define KK     9
#define HH     256
#define WW     512
#define HWSZ   (HH*WW)        // 131072
#define OHW    (HH*WW)        // 131072
#define CK     (CIN*KK)       // 288
#define NKS    (CK/8)         // 36 k-steps of 8

#define TPIX   64             // pixels per tile
#define NCOLS  128            // gemm N = 64 pix * 2 batch
#define CKS    292            // sS word stride (292 % 32 == 4 -> conflict-free frag reads)
#define NTHR   512

#define SS_BYTES   (NCOLS*CKS*4)      // 149504
#define WF_BYTES   (COUT*CK*4)        // 73728 (fragment-layout weights)
#define SMEM_REQ   (SS_BYTES + WF_BYTES + 256)   // 223488 < 227KB

// scratch: x transposed to [B, H*W, C]; weights in mma-fragment layout (tf32)
__device__ __align__(16) float g_xt[(size_t)Bb*HWSZ*CIN];
__device__ __align__(16) float g_wfrag[COUT*CK];

__device__ __forceinline__ uint32_t f2tf32(float v) {
    uint32_t u;
    asm("cvt.rna.tf32.f32 %0, %1;" : "=r"(u) : "f"(v));
    return u;
}

// ---------------- transpose x: [B,C,HW] -> [B,HW,C] ----------------
__global__ void transpose_kernel(const float* __restrict__ x) {
    __shared__ float tile[32][33];
    int b   = blockIdx.y;
    int hw0 = blockIdx.x * 32;
    int tx  = threadIdx.x & 31;
    int ty  = threadIdx.x >> 5;
#pragma unroll
    for (int r = 0; r < 4; r++) {
        int c = r*8 + ty;
        tile[c][tx] = x[((size_t)b*CIN + c)*HWSZ + hw0 + tx];
    }
    __syncthreads();
#pragma unroll
    for (int r = 0; r < 4; r++) {
        int hwi = r*8 + ty;
        g_xt[((size_t)b*HWSZ + hw0 + hwi)*CIN + tx] = tile[tx][hwi];
    }
}

// ---- weights: W[o][c][k] -> A-fragment layout [mg(4)][ks(36)][lane(32)][slot(4)] ----
// slot s: o = mg*16 + (lane>>2) + (s&1)*8 ; ck = ks*8 + (lane&3) + (s>>1)*4
__global__ void wt_kernel(const float* __restrict__ w) {
    int i = blockIdx.x*256 + threadIdx.x;   // 0 .. 18431
    if (i < COUT*CK) {
        int s    = i & 3;
        int lane = (i >> 2) & 31;
        int ks   = (i >> 7) % NKS;
        int mg   = i / (NKS*128);
        int o  = mg*16 + (lane >> 2) + (s & 1)*8;
        int ck = ks*8 + (lane & 3) + (s >> 1)*4;
        int c = ck & 31, k = ck >> 5;
        uint32_t tv = f2tf32(w[(o*CIN + c)*KK + k]);
        g_wfrag[i] = __uint_as_float(tv);
    }
}

// ---------------- main: gather (B tile) + tf32 mma.sync GEMM ----------------
__global__ void __launch_bounds__(NTHR, 1)
mapped_conv_kernel(const float* __restrict__ bias,
                   const float* __restrict__ smap,
                   float* __restrict__ out)
{
    extern __shared__ float sm[];
    float* sS    = sm;                         // [col][ck] stride CKS
    float* sWf   = sm + NCOLS*CKS;             // fragment weights
    float* sBias = sWf + COUT*CK;              // 64 floats

    const int tid  = threadIdx.x;
    const int w    = tid >> 5;
    const int lane = tid & 31;
    const int pix0 = blockIdx.x * TPIX;

    // stage fragment weights (plain vector copy)
    {
        const float4* src = (const float4*)g_wfrag;
        float4* dst = (float4*)sWf;
#pragma unroll
        for (int j = 0; j < WF_BYTES/16/NTHR; j++)      // 9
            dst[j*NTHR + tid] = src[j*NTHR + tid];
    }
    if (tid < COUT) sBias[tid] = bias[tid];

    // ---- gather: warp-task = (col, k); lane = channel. 1152 tasks / 16 warps = 72
    {
        int col = w * 8;           // each warp covers 8 cols x 9 taps
        int k   = 0;
#pragma unroll 2
        for (int it = 0; it < 72; it++) {
            int b = col >> 6;
            int p = col & 63;
            int pix = pix0 + p;
            float2 sxy = ((const float2*)smap)[pix*KK + k];   // warp-uniform
            float bx = floorf(sxy.x), by = floorf(sxy.y);
            float fx = sxy.x - bx,    fy = sxy.y - by;
            int x0 = (int)bx, y0 = (int)by;
            int x0c = min(max(x0, 0), WW-1);
            int x1c = min(x0 + 1, WW-1);
            int y0c = min(max(y0, 0), HH-1);
            int y1c = min(y0 + 1, HH-1);
            uint32_t base = (uint32_t)b*HWSZ*CIN + lane;
            float v00 = g_xt[base + (uint32_t)(y0c*WW + x0c)*CIN];
            float v01 = g_xt[base + (uint32_t)(y0c*WW + x1c)*CIN];
            float v10 = g_xt[base + (uint32_t)(y1c*WW + x0c)*CIN];
            float v11 = g_xt[base + (uint32_t)(y1c*WW + x1c)*CIN];
            float w00 = (1.f-fx)*(1.f-fy), w01 = fx*(1.f-fy);
            float w10 = (1.f-fx)*fy,       w11 = fx*fy;
            float a = w00*v00 + w01*v01 + w10*v10 + w11*v11;
            sS[(uint32_t)col*CKS + k*CIN + lane] = __uint_as_float(f2tf32(a));
            if (++k == KK) { k = 0; ++col; }
        }
    }
    __syncthreads();

    // ---- mma phase: warp (mw, nw) computes m16 x n32, K = 288
    const int mw = w & 3;          // m-group: rows mw*16..+15 (outputs)
    const int nw = w >> 2;         // n-group: cols nw*32..+31
    const uint4* aBase = ((const uint4*)sWf) + (mw*NKS)*32 + lane;
    const uint32_t* sSu = (const uint32_t*)sS;
    uint32_t bOff[4];
#pragma unroll
    for (int g = 0; g < 4; g++)
        bOff[g] = (uint32_t)(nw*32 + g*8 + (lane >> 2))*CKS + (lane & 3);

    float d[4][4];
#pragma unroll
    for (int g = 0; g < 4; g++)
#pragma unroll
        for (int j = 0; j < 4; j++) d[g][j] = 0.f;

#pragma unroll 4
    for (int ks = 0; ks < NKS; ks++) {
        uint4 A = aBase[ks*32];
#pragma unroll
        for (int g = 0; g < 4; g++) {
            uint32_t b0 = sSu[bOff[g] + ks*8];
            uint32_t b1 = sSu[bOff[g] + ks*8 + 4];
            asm volatile(
                "mma.sync.aligned.m16n8k8.row.col.f32.tf32.tf32.f32 "
                "{%0,%1,%2,%3}, {%4,%5,%6,%7}, {%8,%9}, {%0,%1,%2,%3};"
                : "+f"(d[g][0]), "+f"(d[g][1]), "+f"(d[g][2]), "+f"(d[g][3])
                : "r"(A.x), "r"(A.y), "r"(A.z), "r"(A.w), "r"(b0), "r"(b1));
        }
    }

    // ---- epilogue: D row = output channel o, col = (b, pixel)
    {
        int o0 = mw*16 + (lane >> 2);
        float bias0 = sBias[o0];
        float bias1 = sBias[o0 + 8];
#pragma unroll
        for (int g = 0; g < 4; g++) {
            int n  = nw*32 + g*8 + (lane & 3)*2;
            int bb = n >> 6;
            int p  = n & 63;
            float* op = out + ((size_t)(bb*COUT + o0))*OHW + pix0 + p;
            float2 v0 = make_float2(d[g][0] + bias0, d[g][1] + bias0);
            float2 v1 = make_float2(d[g][2] + bias1, d[g][3] + bias1);
            *(float2*)op = v0;
            *(float2*)(op + (size_t)8*OHW) = v1;
        }
    }
}

extern "C" void kernel_launch(void* const* d_in, const int* in_sizes, int n_in,
                              void* d_out, int out_size) {
    const float* x    = (const float*)d_in[0];
    const float* w    = (const float*)d_in[1];
    const float* bias = (const float*)d_in[2];
    const float* smap = (const float*)d_in[3];
    float* out = (float*)d_out;

    cudaFuncSetAttribute(mapped_conv_kernel,
                         cudaFuncAttributeMaxDynamicSharedMemorySize, SMEM_REQ);

    transpose_kernel<<<dim3(HWSZ/32, Bb), 256>>>(x);
    wt_kernel<<<(COUT*CK + 255)/256, 256>>>(w);
    mapped_conv_kernel<<<OHW/TPIX, NTHR, SMEM_REQ>>>(bias, smap, out);
}

// round 4
// speedup vs baseline: 1.9543x; 1.5953x over previous
#include <cuda_runtime.h>
#include <cstdint>

#define Bb     2
#define CIN    32
#define COUT   64
#define KK     9
#define HH     256
#define WW     512
#define HWSZ   (HH*WW)        // 131072
#define OHW    (HH*WW)        // 131072
#define CK     (CIN*KK)       // 288
#define NKS    (CK/8)         // 36 k-steps of 8

#define TPIX   64             // pixels per tile
#define NCOLS  128            // gemm N = 64 pix * 2 batch
#define SLW    36             // per-slice sB word stride (36%32==4 -> conflict-free)
#define NTHR   512

// smem floats: weights 18432 + sB 2*128*36=9216 + idx 2304 + wgt 2304 + bias 64
#define SM_WF    0
#define SM_SB    (SM_WF + COUT*CK)
#define SM_IDX   (SM_SB + 2*NCOLS*SLW)
#define SM_WGT   (SM_IDX + TPIX*KK*4)
#define SM_BIAS  (SM_WGT + TPIX*KK*4)
#define SM_TOT   (SM_BIAS + COUT)
#define SMEM_REQ (SM_TOT*4)

// scratch: x transposed to [B, H*W, C]; weights in mma-fragment layout (tf32)
__device__ __align__(16) float g_xt[(size_t)Bb*HWSZ*CIN];
__device__ __align__(16) float g_wfrag[COUT*CK];

__device__ __forceinline__ uint32_t f2tf32(float v) {
    uint32_t u;
    asm("cvt.rna.tf32.f32 %0, %1;" : "=r"(u) : "f"(v));
    return u;
}

// ---------------- transpose x: [B,C,HW] -> [B,HW,C] ----------------
__global__ void transpose_kernel(const float* __restrict__ x) {
    __shared__ float tile[32][33];
    int b   = blockIdx.y;
    int hw0 = blockIdx.x * 32;
    int tx  = threadIdx.x & 31;
    int ty  = threadIdx.x >> 5;
#pragma unroll
    for (int r = 0; r < 4; r++) {
        int c = r*8 + ty;
        tile[c][tx] = x[((size_t)b*CIN + c)*HWSZ + hw0 + tx];
    }
    __syncthreads();
#pragma unroll
    for (int r = 0; r < 4; r++) {
        int hwi = r*8 + ty;
        g_xt[((size_t)b*HWSZ + hw0 + hwi)*CIN + tx] = tile[tx][hwi];
    }
}

// ---- weights: W[o][c][k] -> A-fragment layout [mg(4)][ks(36)][lane(32)][slot(4)] ----
// slot s: o = mg*16 + (lane>>2) + (s&1)*8 ; ck = ks*8 + (lane&3) + (s>>1)*4
__global__ void wt_kernel(const float* __restrict__ w) {
    int i = blockIdx.x*256 + threadIdx.x;
    if (i < COUT*CK) {
        int s    = i & 3;
        int lane = (i >> 2) & 31;
        int ks   = (i >> 7) % NKS;
        int mg   = i / (NKS*128);
        int o  = mg*16 + (lane >> 2) + (s & 1)*8;
        int ck = ks*8 + (lane & 3) + (s >> 1)*4;
        int c = ck & 31, k = ck >> 5;
        g_wfrag[i] = __uint_as_float(f2tf32(w[(o*CIN + c)*KK + k]));
    }
}

// ---------------- main: pipelined gather + tf32 mma.sync ----------------
__global__ void __launch_bounds__(NTHR, 1)
mapped_conv_kernel(const float* __restrict__ bias,
                   const float* __restrict__ smap,
                   float* __restrict__ out)
{
    extern __shared__ float sm[];
    float*  sWf   = sm + SM_WF;
    float*  sB    = sm + SM_SB;
    int4*   sIdx4 = (int4*)(sm + SM_IDX);
    float4* sWgt4 = (float4*)(sm + SM_WGT);
    float*  sBias = sm + SM_BIAS;

    const int tid  = threadIdx.x;
    const int w    = tid >> 5;
    const int lane = tid & 31;
    const int pix0 = blockIdx.x * TPIX;

    // stage fragment weights
    {
        const float4* src = (const float4*)g_wfrag;
        float4* dst = (float4*)sWf;
#pragma unroll
        for (int j = 0; j < COUT*CK/4/NTHR; j++)   // 9
            dst[j*NTHR + tid] = src[j*NTHR + tid];
    }
    if (tid < COUT) sBias[tid] = bias[tid];

    // precompute bilinear tables: task t = p*9+k, 576 tasks
    for (int t = tid; t < TPIX*KK; t += NTHR) {
        int p = t / KK, k = t - p*KK;
        float2 sxy = ((const float2*)smap)[(pix0 + p)*KK + k];
        float bx = floorf(sxy.x), by = floorf(sxy.y);
        float fx = sxy.x - bx,    fy = sxy.y - by;
        int x0 = (int)bx, y0 = (int)by;
        int x0c = min(max(x0, 0), WW-1);
        int x1c = min(x0 + 1, WW-1);
        int y0c = min(max(y0, 0), HH-1);
        int y1c = min(y0 + 1, HH-1);
        sIdx4[t] = make_int4((y0c*WW + x0c)*CIN, (y0c*WW + x1c)*CIN,
                             (y1c*WW + x0c)*CIN, (y1c*WW + x1c)*CIN);
        sWgt4[t] = make_float4((1.f-fx)*(1.f-fy), fx*(1.f-fy),
                               (1.f-fx)*fy,       fx*fy);
    }
    __syncthreads();

    // warp's gather assignment: batch b, 8 pixel-rows
    const int gb_b  = w >> 3;            // 0..1
    const int gp0   = (w & 7) * 8;       // pixel base
    const int gcol0 = gb_b*TPIX + gp0;   // gemm col base
    const float* __restrict__ gxb = g_xt + (size_t)gb_b*HWSZ*CIN + lane;

    // mma assignment
    const int mw = w & 3;                // rows (outputs) mw*16..+15
    const int nw = w >> 2;               // cols nw*32..+31
    const uint32_t* sBu = (const uint32_t*)sB;
    uint32_t bOff[4];
#pragma unroll
    for (int g = 0; g < 4; g++)
        bOff[g] = (uint32_t)(nw*32 + g*8 + (lane >> 2))*SLW + (lane & 3);

    float d[4][4];
#pragma unroll
    for (int g = 0; g < 4; g++)
#pragma unroll
        for (int j = 0; j < 4; j++) d[g][j] = 0.f;

    float vs[32];

    // prologue: gather slice 0 -> buf 0
#pragma unroll
    for (int j = 0; j < 8; j++) {
        int4 id = sIdx4[(gp0 + j)*KK + 0];
        vs[j*4+0] = gxb[id.x];
        vs[j*4+1] = gxb[id.y];
        vs[j*4+2] = gxb[id.z];
        vs[j*4+3] = gxb[id.w];
    }
#pragma unroll
    for (int j = 0; j < 8; j++) {
        float4 wt = sWgt4[(gp0 + j)*KK + 0];
        float a = wt.x*vs[j*4] + wt.y*vs[j*4+1] + wt.z*vs[j*4+2] + wt.w*vs[j*4+3];
        sB[(uint32_t)(gcol0 + j)*SLW + lane] = __uint_as_float(f2tf32(a));
    }
    __syncthreads();

    for (int k = 0; k < KK; k++) {
        const int kn = k + 1;
        // issue gather loads for slice kn (in flight during MMA)
        if (kn < KK) {
#pragma unroll
            for (int j = 0; j < 8; j++) {
                int4 id = sIdx4[(gp0 + j)*KK + kn];
                vs[j*4+0] = gxb[id.x];
                vs[j*4+1] = gxb[id.y];
                vs[j*4+2] = gxb[id.z];
                vs[j*4+3] = gxb[id.w];
            }
        }
        // MMA on slice k (buf k&1)
        {
            const uint32_t bufb = (uint32_t)(k & 1) * (NCOLS*SLW);
            const uint4* aB = ((const uint4*)sWf) + (uint32_t)(mw*NKS + k*4)*32 + lane;
#pragma unroll
            for (int ksl = 0; ksl < 4; ksl++) {
                uint4 A = aB[ksl*32];
#pragma unroll
                for (int g = 0; g < 4; g++) {
                    uint32_t b0 = sBu[bufb + bOff[g] + ksl*8];
                    uint32_t b1 = sBu[bufb + bOff[g] + ksl*8 + 4];
                    asm volatile(
                        "mma.sync.aligned.m16n8k8.row.col.f32.tf32.tf32.f32 "
                        "{%0,%1,%2,%3}, {%4,%5,%6,%7}, {%8,%9}, {%0,%1,%2,%3};"
                        : "+f"(d[g][0]), "+f"(d[g][1]), "+f"(d[g][2]), "+f"(d[g][3])
                        : "r"(A.x), "r"(A.y), "r"(A.z), "r"(A.w), "r"(b0), "r"(b1));
                }
            }
        }
        // combine + store slice kn -> buf kn&1
        if (kn < KK) {
            float* dstb = sB + (uint32_t)(kn & 1)*(NCOLS*SLW);
#pragma unroll
            for (int j = 0; j < 8; j++) {
                float4 wt = sWgt4[(gp0 + j)*KK + kn];
                float a = wt.x*vs[j*4] + wt.y*vs[j*4+1] + wt.z*vs[j*4+2] + wt.w*vs[j*4+3];
                dstb[(uint32_t)(gcol0 + j)*SLW + lane] = __uint_as_float(f2tf32(a));
            }
        }
        __syncthreads();
    }

    // epilogue: D row = output channel o, col = (b, pixel)
    {
        int o0 = mw*16 + (lane >> 2);
        float bias0 = sBias[o0];
        float bias1 = sBias[o0 + 8];
#pragma unroll
        for (int g = 0; g < 4; g++) {
            int n  = nw*32 + g*8 + (lane & 3)*2;
            int bb = n >> 6;
            int p  = n & 63;
            float* op = out + ((size_t)(bb*COUT + o0))*OHW + pix0 + p;
            *(float2*)op = make_float2(d[g][0] + bias0, d[g][1] + bias0);
            *(float2*)(op + (size_t)8*OHW) = make_float2(d[g][2] + bias1, d[g][3] + bias1);
        }
    }
}

extern "C" void kernel_launch(void* const* d_in, const int* in_sizes, int n_in,
                              void* d_out, int out_size) {
    const float* x    = (const float*)d_in[0];
    const float* w    = (const float*)d_in[1];
    const float* bias = (const float*)d_in[2];
    const float* smap = (const float*)d_in[3];
    float* out = (float*)d_out;

    cudaFuncSetAttribute(mapped_conv_kernel,
                         cudaFuncAttributeMaxDynamicSharedMemorySize, SMEM_REQ);

    transpose_kernel<<<dim3(HWSZ/32, Bb), 256>>>(x);
    wt_kernel<<<(COUT*CK + 255)/256, 256>>>(w);
    mapped_conv_kernel<<<OHW/TPIX, NTHR, SMEM_REQ>>>(bias, smap, out);
}

// round 5
// speedup vs baseline: 2.3689x; 1.2121x over previous
#include <cuda_runtime.h>
#include <cstdint>

#define Bb     2
#define CIN    32
#define COUT   64
#define KK     9
#define HH     256
#define WW     512
#define HWSZ   (HH*WW)        // 131072
#define OHW    (HH*WW)        // 131072
#define CK     (CIN*KK)       // 288
#define NKS    (CK/8)         // 36 k-steps of 8

#define TPIX   64             // pixels per tile
#define NCOLS  128            // gemm N = 64 pix * 2 batch
#define NSTG   5              // ceil(9/2) two-tap stages
#define SLW2   68             // per-stage sB word stride (68%32==4 -> conflict-free)
#define NTHR   512

// smem floats
#define SM_WF    0
#define SM_SB    (SM_WF + COUT*CK)              // 18432
#define SM_IDX   (SM_SB + 2*NCOLS*SLW2)         // +17408
#define SM_WGT   (SM_IDX + TPIX*KK*4)           // +2304
#define SM_BIAS  (SM_WGT + TPIX*KK*4)           // +2304
#define SM_TOT   (SM_BIAS + COUT)
#define SMEM_REQ (SM_TOT*4)                     // ~162 KB

// scratch: x transposed to [B, H*W, C]; weights in mma-fragment layout (tf32)
__device__ __align__(16) float g_xt[(size_t)Bb*HWSZ*CIN];
__device__ __align__(16) float g_wfrag[COUT*CK];

__device__ __forceinline__ uint32_t f2tf32(float v) {
    uint32_t u;
    asm("cvt.rna.tf32.f32 %0, %1;" : "=r"(u) : "f"(v));
    return u;
}

// ---------------- transpose x: [B,C,HW] -> [B,HW,C] ----------------
__global__ void transpose_kernel(const float* __restrict__ x) {
    __shared__ float tile[32][33];
    int b   = blockIdx.y;
    int hw0 = blockIdx.x * 32;
    int tx  = threadIdx.x & 31;
    int ty  = threadIdx.x >> 5;
#pragma unroll
    for (int r = 0; r < 4; r++) {
        int c = r*8 + ty;
        tile[c][tx] = x[((size_t)b*CIN + c)*HWSZ + hw0 + tx];
    }
    __syncthreads();
#pragma unroll
    for (int r = 0; r < 4; r++) {
        int hwi = r*8 + ty;
        g_xt[((size_t)b*HWSZ + hw0 + hwi)*CIN + tx] = tile[tx][hwi];
    }
}

// ---- weights: W[o][c][k] -> A-fragment layout [mg(4)][ks(36)][lane(32)][slot(4)] ----
__global__ void wt_kernel(const float* __restrict__ w) {
    int i = blockIdx.x*256 + threadIdx.x;
    if (i < COUT*CK) {
        int s    = i & 3;
        int lane = (i >> 2) & 31;
        int ks   = (i >> 7) % NKS;
        int mg   = i / (NKS*128);
        int o  = mg*16 + (lane >> 2) + (s & 1)*8;
        int ck = ks*8 + (lane & 3) + (s >> 1)*4;
        int c = ck & 31, k = ck >> 5;
        g_wfrag[i] = __uint_as_float(f2tf32(w[(o*CIN + c)*KK + k]));
    }
}

// ---------------- main: pipelined float4 gather + tf32 mma.sync ----------------
__global__ void __launch_bounds__(NTHR, 1)
mapped_conv_kernel(const float* __restrict__ bias,
                   const float* __restrict__ smap,
                   float* __restrict__ out)
{
    extern __shared__ float sm[];
    float*  sWf   = sm + SM_WF;
    float*  sB    = sm + SM_SB;
    int4*   sIdx4 = (int4*)(sm + SM_IDX);
    float4* sWgt4 = (float4*)(sm + SM_WGT);
    float*  sBias = sm + SM_BIAS;

    const int tid  = threadIdx.x;
    const int w    = tid >> 5;
    const int lane = tid & 31;
    const int pix0 = blockIdx.x * TPIX;

    // stage fragment weights
    {
        const float4* src = (const float4*)g_wfrag;
        float4* dst = (float4*)sWf;
#pragma unroll
        for (int j = 0; j < COUT*CK/4/NTHR; j++)   // 9
            dst[j*NTHR + tid] = src[j*NTHR + tid];
    }
    if (tid < COUT) sBias[tid] = bias[tid];

    // bilinear tables: task t = p*9+k (spatial indices, not scaled)
    for (int t = tid; t < TPIX*KK; t += NTHR) {
        int p = t / KK, k = t - p*KK;
        float2 sxy = ((const float2*)smap)[(pix0 + p)*KK + k];
        float bx = floorf(sxy.x), by = floorf(sxy.y);
        float fx = sxy.x - bx,    fy = sxy.y - by;
        int x0 = (int)bx, y0 = (int)by;
        int x0c = min(max(x0, 0), WW-1);
        int x1c = min(x0 + 1, WW-1);
        int y0c = min(max(y0, 0), HH-1);
        int y1c = min(y0 + 1, HH-1);
        sIdx4[t] = make_int4(y0c*WW + x0c, y0c*WW + x1c,
                             y1c*WW + x0c, y1c*WW + x1c);
        sWgt4[t] = make_float4((1.f-fx)*(1.f-fy), fx*(1.f-fy),
                               (1.f-fx)*fy,       fx*fy);
    }
    __syncthreads();

    // gather mapping: warp -> (batch, 8 pixels); lane = cq(8) x cs(4)
    const int gb_b  = w >> 3;
    const int gp0   = (w & 7) * 8;
    const int gcol0 = gb_b*TPIX + gp0;
    const int cq    = lane & 7;
    const int cs    = lane >> 3;
    const float4* __restrict__ gxb4 = (const float4*)g_xt + (size_t)gb_b*HWSZ*8 + cq;

    // mma mapping
    const int mw = w & 3;
    const int nw = w >> 2;
    const uint32_t* sBu = (const uint32_t*)sB;
    uint32_t bOff[4];
#pragma unroll
    for (int g = 0; g < 4; g++)
        bOff[g] = (uint32_t)(nw*32 + g*8 + (lane >> 2))*SLW2 + (lane & 3);

    float d[4][4];
#pragma unroll
    for (int g = 0; g < 4; g++)
#pragma unroll
        for (int j = 0; j < 4; j++) d[g][j] = 0.f;

    float4 vs[4][4];   // [iter][corner]

    // ---- prologue: issue + store stage 0 (taps 0,1)
#pragma unroll
    for (int i = 0; i < 4; i++) {
        int tap = i >> 1;
        int p   = gp0 + (i & 1)*4 + cs;
        int4 id = sIdx4[p*KK + tap];
        vs[i][0] = gxb4[(size_t)id.x*8];
        vs[i][1] = gxb4[(size_t)id.y*8];
        vs[i][2] = gxb4[(size_t)id.z*8];
        vs[i][3] = gxb4[(size_t)id.w*8];
    }
#pragma unroll
    for (int i = 0; i < 4; i++) {
        int tap = i >> 1;
        int p   = gp0 + (i & 1)*4 + cs;
        int col = gcol0 + (i & 1)*4 + cs;
        float4 wt = sWgt4[p*KK + tap];
        float ax = wt.x*vs[i][0].x + wt.y*vs[i][1].x + wt.z*vs[i][2].x + wt.w*vs[i][3].x;
        float ay = wt.x*vs[i][0].y + wt.y*vs[i][1].y + wt.z*vs[i][2].y + wt.w*vs[i][3].y;
        float az = wt.x*vs[i][0].z + wt.y*vs[i][1].z + wt.z*vs[i][2].z + wt.w*vs[i][3].z;
        float aw = wt.x*vs[i][0].w + wt.y*vs[i][1].w + wt.z*vs[i][2].w + wt.w*vs[i][3].w;
        float4* dst = (float4*)&sB[(uint32_t)col*SLW2 + (tap & 1)*32 + cq*4];
        *dst = make_float4(__uint_as_float(f2tf32(ax)), __uint_as_float(f2tf32(ay)),
                           __uint_as_float(f2tf32(az)), __uint_as_float(f2tf32(aw)));
    }
    __syncthreads();

    // ---- main loop: 5 stages, fully unrolled
#pragma unroll
    for (int s = 0; s < NSTG; s++) {
        const int t0n = (s + 1) * 2;          // next stage's first tap
        // issue next stage's loads
        if (s + 1 < NSTG) {
#pragma unroll
            for (int i = 0; i < 4; i++) {
                int tap = t0n + (i >> 1);
                if (tap < KK) {
                    int p   = gp0 + (i & 1)*4 + cs;
                    int4 id = sIdx4[p*KK + tap];
                    vs[i][0] = gxb4[(size_t)id.x*8];
                    vs[i][1] = gxb4[(size_t)id.y*8];
                    vs[i][2] = gxb4[(size_t)id.z*8];
                    vs[i][3] = gxb4[(size_t)id.w*8];
                }
            }
        }
        // MMA on stage s
        {
            const uint32_t bufb = (uint32_t)(s & 1) * (NCOLS*SLW2);
            const uint4* aB = ((const uint4*)sWf) + (uint32_t)(mw*NKS + s*8)*32 + lane;
            const int nk = (s*8 + 8 <= NKS) ? 8 : (NKS - s*8);
#pragma unroll
            for (int ksl = 0; ksl < 8; ksl++) {
                if (ksl < nk) {
                    uint4 A = aB[ksl*32];
#pragma unroll
                    for (int g = 0; g < 4; g++) {
                        uint32_t b0 = sBu[bufb + bOff[g] + ksl*8];
                        uint32_t b1 = sBu[bufb + bOff[g] + ksl*8 + 4];
                        asm volatile(
                            "mma.sync.aligned.m16n8k8.row.col.f32.tf32.tf32.f32 "
                            "{%0,%1,%2,%3}, {%4,%5,%6,%7}, {%8,%9}, {%0,%1,%2,%3};"
                            : "+f"(d[g][0]), "+f"(d[g][1]), "+f"(d[g][2]), "+f"(d[g][3])
                            : "r"(A.x), "r"(A.y), "r"(A.z), "r"(A.w), "r"(b0), "r"(b1));
                    }
                }
            }
        }
        // combine + store next stage
        if (s + 1 < NSTG) {
            float* dstb = sB + (uint32_t)((s + 1) & 1)*(NCOLS*SLW2);
#pragma unroll
            for (int i = 0; i < 4; i++) {
                int tap = t0n + (i >> 1);
                if (tap < KK) {
                    int p   = gp0 + (i & 1)*4 + cs;
                    int col = gcol0 + (i & 1)*4 + cs;
                    float4 wt = sWgt4[p*KK + tap];
                    float ax = wt.x*vs[i][0].x + wt.y*vs[i][1].x + wt.z*vs[i][2].x + wt.w*vs[i][3].x;
                    float ay = wt.x*vs[i][0].y + wt.y*vs[i][1].y + wt.z*vs[i][2].y + wt.w*vs[i][3].y;
                    float az = wt.x*vs[i][0].z + wt.y*vs[i][1].z + wt.z*vs[i][2].z + wt.w*vs[i][3].z;
                    float aw = wt.x*vs[i][0].w + wt.y*vs[i][1].w + wt.z*vs[i][2].w + wt.w*vs[i][3].w;
                    float4* dst = (float4*)&dstb[(uint32_t)col*SLW2 + (tap & 1)*32 + cq*4];
                    *dst = make_float4(__uint_as_float(f2tf32(ax)), __uint_as_float(f2tf32(ay)),
                                       __uint_as_float(f2tf32(az)), __uint_as_float(f2tf32(aw)));
                }
            }
            __syncthreads();
        }
    }

    // ---- epilogue
    {
        int o0 = mw*16 + (lane >> 2);
        float bias0 = sBias[o0];
        float bias1 = sBias[o0 + 8];
#pragma unroll
        for (int g = 0; g < 4; g++) {
            int n  = nw*32 + g*8 + (lane & 3)*2;
            int bb = n >> 6;
            int p  = n & 63;
            float* op = out + ((size_t)(bb*COUT + o0))*OHW + pix0 + p;
            *(float2*)op = make_float2(d[g][0] + bias0, d[g][1] + bias0);
            *(float2*)(op + (size_t)8*OHW) = make_float2(d[g][2] + bias1, d[g][3] + bias1);
        }
    }
}

extern "C" void kernel_launch(void* const* d_in, const int* in_sizes, int n_in,
                              void* d_out, int out_size) {
    const float* x    = (const float*)d_in[0];
    const float* w    = (const float*)d_in[1];
    const float* bias = (const float*)d_in[2];
    const float* smap = (const float*)d_in[3];
    float* out = (float*)d_out;

    cudaFuncSetAttribute(mapped_conv_kernel,
                         cudaFuncAttributeMaxDynamicSharedMemorySize, SMEM_REQ);

    transpose_kernel<<<dim3(HWSZ/32, Bb), 256>>>(x);
    wt_kernel<<<(COUT*CK + 255)/256, 256>>>(w);
    mapped_conv_kernel<<<OHW/TPIX, NTHR, SMEM_REQ>>>(bias, smap, out);
}

// round 7
// speedup vs baseline: 2.7212x; 1.1488x over previous
#include <cuda_runtime.h>
#include <cstdint>

#define Bb     2
#define CIN    32
#define COUT   64
#define KK     9
#define HH     256
#define WW     512
#define HWSZ   (HH*WW)        // 131072
#define OHW    (HH*WW)        // 131072
#define CK     (CIN*KK)       // 288
#define NKS    (CK/8)         // 36

#define TPIX   32             // pixels per tile
#define NCOLS  64             // gemm N = 32 pix * 2 batch
#define SLW    36             // sB word stride (36%32==4 -> conflict-free frag reads)
#define NTHR   256

// scratch: x transposed to [B, H*W, C]; weights in mma-fragment layout (tf32)
__device__ __align__(16) float g_xt[(size_t)Bb*HWSZ*CIN];
__device__ __align__(16) float g_wfrag[COUT*CK];

__device__ __forceinline__ uint32_t f2tf32(float v) {
    uint32_t u;
    asm("cvt.rna.tf32.f32 %0, %1;" : "=r"(u) : "f"(v));
    return u;
}

// ---------------- transpose x: [B,C,HW] -> [B,HW,C] ----------------
__global__ void transpose_kernel(const float* __restrict__ x) {
    __shared__ float tile[32][33];
    int b   = blockIdx.y;
    int hw0 = blockIdx.x * 32;
    int tx  = threadIdx.x & 31;
    int ty  = threadIdx.x >> 5;
#pragma unroll
    for (int r = 0; r < 4; r++) {
        int c = r*8 + ty;
        tile[c][tx] = x[((size_t)b*CIN + c)*HWSZ + hw0 + tx];
    }
    __syncthreads();
#pragma unroll
    for (int r = 0; r < 4; r++) {
        int hwi = r*8 + ty;
        g_xt[((size_t)b*HWSZ + hw0 + hwi)*CIN + tx] = tile[tx][hwi];
    }
}

// ---- weights: W[o][c][k] -> A-fragment layout [mg(4)][ks(36)][lane(32)][slot(4)] ----
// slot s: o = mg*16 + (lane>>2) + (s&1)*8 ; ck = ks*8 + (lane&3) + (s>>1)*4
__global__ void wt_kernel(const float* __restrict__ w) {
    int i = blockIdx.x*256 + threadIdx.x;
    if (i < COUT*CK) {
        int s    = i & 3;
        int lane = (i >> 2) & 31;
        int ks   = (i >> 7) % NKS;
        int mg   = i / (NKS*128);
        int o  = mg*16 + (lane >> 2) + (s & 1)*8;
        int ck = ks*8 + (lane & 3) + (s >> 1)*4;
        int c = ck & 31, k = ck >> 5;
        g_wfrag[i] = __uint_as_float(f2tf32(w[(o*CIN + c)*KK + k]));
    }
}

// ---------------- main: pipelined gather + tf32 mma.sync, 2 CTAs/SM ----------------
__global__ void __launch_bounds__(NTHR, 2)
mapped_conv_kernel(const float* __restrict__ bias,
                   const float* __restrict__ smap,
                   float* __restrict__ out)
{
    __shared__ float  sB[2*NCOLS*SLW];     // 4608 fl, double-buffered sampled tile
    __shared__ int4   sIdx4[TPIX*KK];      // 288
    __shared__ float4 sWgt4[TPIX*KK];      // 288
    __shared__ float  sBias[COUT];

    const int tid  = threadIdx.x;
    const int w    = tid >> 5;             // 0..7
    const int lane = tid & 31;
    const int pix0 = blockIdx.x * TPIX;

    if (tid < COUT) sBias[tid] = bias[tid];

    // bilinear tables: task t = p*9+k, 288 tasks
    for (int t = tid; t < TPIX*KK; t += NTHR) {
        int p = t / KK, k = t - p*KK;
        float2 sxy = ((const float2*)smap)[(pix0 + p)*KK + k];
        float bx = floorf(sxy.x), by = floorf(sxy.y);
        float fx = sxy.x - bx,    fy = sxy.y - by;
        int x0 = (int)bx, y0 = (int)by;
        int x0c = min(max(x0, 0), WW-1);
        int x1c = min(x0 + 1, WW-1);
        int y0c = min(max(y0, 0), HH-1);
        int y1c = min(y0 + 1, HH-1);
        sIdx4[t] = make_int4(y0c*WW + x0c, y0c*WW + x1c,
                             y1c*WW + x0c, y1c*WW + x1c);
        sWgt4[t] = make_float4((1.f-fx)*(1.f-fy), fx*(1.f-fy),
                               (1.f-fx)*fy,       fx*fy);
    }

    // gather mapping: warp -> 8 cols (batch = w>>2); lane = cq(8) x cs(4)
    const int gb_b  = w >> 2;
    const int gcol0 = w * 8;               // gemm col base (b*32 + pixel)
    const int gp0   = gcol0 & 31;          // pixel base within tile
    const int cq    = lane & 7;
    const int cs    = lane >> 3;
    const float4* __restrict__ gxb4 = (const float4*)g_xt + (size_t)gb_b*HWSZ*8 + cq;

    // mma mapping: mw = rows (outputs) mw*16..+15 ; nw = cols nw*32..+31
    const int mw = w & 3;
    const int nw = w >> 2;
    const uint32_t* sBu = (const uint32_t*)sB;
    uint32_t bOff[4];
#pragma unroll
    for (int g = 0; g < 4; g++)
        bOff[g] = (uint32_t)(nw*32 + g*8 + (lane >> 2))*SLW + (lane & 3);

    const uint4* __restrict__ gw4 = (const uint4*)g_wfrag + (uint32_t)(mw*NKS)*32 + lane;

    float d[4][4];
#pragma unroll
    for (int g = 0; g < 4; g++)
#pragma unroll
        for (int j = 0; j < 4; j++) d[g][j] = 0.f;

    float4 vs[2][4];     // [col-iter][corner]
    uint4  Acur[4], Anx[4];

    __syncthreads();     // tables ready

    // ---- prologue: gather tap 0, prefetch A(tap 0)
#pragma unroll
    for (int i = 0; i < 2; i++) {
        int p = gp0 + i*4 + cs;
        int4 id = sIdx4[p*KK];
        vs[i][0] = gxb4[(size_t)id.x*8];
        vs[i][1] = gxb4[(size_t)id.y*8];
        vs[i][2] = gxb4[(size_t)id.z*8];
        vs[i][3] = gxb4[(size_t)id.w*8];
    }
#pragma unroll
    for (int ksl = 0; ksl < 4; ksl++) Anx[ksl] = gw4[ksl*32];
#pragma unroll
    for (int i = 0; i < 2; i++) {
        int p   = gp0 + i*4 + cs;
        int col = gcol0 + i*4 + cs;
        float4 wt = sWgt4[p*KK];
        float ax = wt.x*vs[i][0].x + wt.y*vs[i][1].x + wt.z*vs[i][2].x + wt.w*vs[i][3].x;
        float ay = wt.x*vs[i][0].y + wt.y*vs[i][1].y + wt.z*vs[i][2].y + wt.w*vs[i][3].y;
        float az = wt.x*vs[i][0].z + wt.y*vs[i][1].z + wt.z*vs[i][2].z + wt.w*vs[i][3].z;
        float aw = wt.x*vs[i][0].w + wt.y*vs[i][1].w + wt.z*vs[i][2].w + wt.w*vs[i][3].w;
        *(float4*)&sB[(uint32_t)col*SLW + cq*4] =
            make_float4(__uint_as_float(f2tf32(ax)), __uint_as_float(f2tf32(ay)),
                        __uint_as_float(f2tf32(az)), __uint_as_float(f2tf32(aw)));
    }
    __syncthreads();

    // ---- main loop: 9 taps
#pragma unroll
    for (int k = 0; k < KK; k++) {
#pragma unroll
        for (int ksl = 0; ksl < 4; ksl++) Acur[ksl] = Anx[ksl];
        // issue next tap's gather + A prefetch
        if (k + 1 < KK) {
#pragma unroll
            for (int i = 0; i < 2; i++) {
                int p = gp0 + i*4 + cs;
                int4 id = sIdx4[p*KK + k + 1];
                vs[i][0] = gxb4[(size_t)id.x*8];
                vs[i][1] = gxb4[(size_t)id.y*8];
                vs[i][2] = gxb4[(size_t)id.z*8];
                vs[i][3] = gxb4[(size_t)id.w*8];
            }
#pragma unroll
            for (int ksl = 0; ksl < 4; ksl++) Anx[ksl] = gw4[((k+1)*4 + ksl)*32];
        }
        // MMA tap k (buf k&1)
        {
            const uint32_t bufb = (uint32_t)(k & 1) * (NCOLS*SLW);
#pragma unroll
            for (int ksl = 0; ksl < 4; ksl++) {
#pragma unroll
                for (int g = 0; g < 4; g++) {
                    uint32_t b0 = sBu[bufb + bOff[g] + ksl*8];
                    uint32_t b1 = sBu[bufb + bOff[g] + ksl*8 + 4];
                    asm volatile(
                        "mma.sync.aligned.m16n8k8.row.col.f32.tf32.tf32.f32 "
                        "{%0,%1,%2,%3}, {%4,%5,%6,%7}, {%8,%9}, {%0,%1,%2,%3};"
                        : "+f"(d[g][0]), "+f"(d[g][1]), "+f"(d[g][2]), "+f"(d[g][3])
                        : "r"(Acur[ksl].x), "r"(Acur[ksl].y),
                          "r"(Acur[ksl].z), "r"(Acur[ksl].w), "r"(b0), "r"(b1));
                }
            }
        }
        // combine + store tap k+1 -> buf (k+1)&1
        if (k + 1 < KK) {
            float* dstb = sB + (uint32_t)((k + 1) & 1)*(NCOLS*SLW);
#pragma unroll
            for (int i = 0; i < 2; i++) {
                int p   = gp0 + i*4 + cs;
                int col = gcol0 + i*4 + cs;
                float4 wt = sWgt4[p*KK + k + 1];
                float ax = wt.x*vs[i][0].x + wt.y*vs[i][1].x + wt.z*vs[i][2].x + wt.w*vs[i][3].x;
                float ay = wt.x*vs[i][0].y + wt.y*vs[i][1].y + wt.z*vs[i][2].y + wt.w*vs[i][3].y;
                float az = wt.x*vs[i][0].z + wt.y*vs[i][1].z + wt.z*vs[i][2].z + wt.w*vs[i][3].z;
                float aw = wt.x*vs[i][0].w + wt.y*vs[i][1].w + wt.z*vs[i][2].w + wt.w*vs[i][3].w;
                *(float4*)&dstb[(uint32_t)col*SLW + cq*4] =
                    make_float4(__uint_as_float(f2tf32(ax)), __uint_as_float(f2tf32(ay)),
                                __uint_as_float(f2tf32(az)), __uint_as_float(f2tf32(aw)));
            }
            __syncthreads();
        }
    }

    // ---- epilogue: D row = output channel o, col = (b, pixel)
    {
        int o0 = mw*16 + (lane >> 2);
        float bias0 = sBias[o0];
        float bias1 = sBias[o0 + 8];
#pragma unroll
        for (int g = 0; g < 4; g++) {
            int n  = nw*32 + g*8 + (lane & 3)*2;
            int bb = n >> 5;
            int p  = n & 31;
            float* op = out + ((size_t)(bb*COUT + o0))*OHW + pix0 + p;
            *(float2*)op = make_float2(d[g][0] + bias0, d[g][1] + bias0);
            *(float2*)(op + (size_t)8*OHW) = make_float2(d[g][2] + bias1, d[g][3] + bias1);
        }
    }
}

extern "C" void kernel_launch(void* const* d_in, const int* in_sizes, int n_in,
                              void* d_out, int out_size) {
    const float* x    = (const float*)d_in[0];
    const float* w    = (const float*)d_in[1];
    const float* bias = (const float*)d_in[2];
    const float* smap = (const float*)d_in[3];
    float* out = (float*)d_out;

    transpose_kernel<<<dim3(HWSZ/32, Bb), 256>>>(x);
    wt_kernel<<<(COUT*CK + 255)/256, 256>>>(w);
    mapped_conv_kernel<<<OHW/TPIX, NTHR>>>(bias, smap, out);
}

// round 8
// speedup vs baseline: 2.8231x; 1.0374x over previous
#include <cuda_runtime.h>
#include <cstdint>

#define Bb     2
#define CIN    32
#define COUT   64
#define KK     9
#define HH     256
#define WW     512
#define HWSZ   (HH*WW)        // 131072
#define OHW    (HH*WW)        // 131072
#define CK     (CIN*KK)       // 288
#define NKS    (CK/8)         // 36

#define TPIX   16             // pixels per tile
#define NCOLS  32             // gemm N = 16 pix * 2 batch
#define SLW    36             // sB word stride (36%32==4 -> conflict-free frag reads)
#define NTHR   128

// scratch: x transposed to [B, H*W, C]; weights in mma-fragment layout (tf32)
__device__ __align__(16) float g_xt[(size_t)Bb*HWSZ*CIN];
__device__ __align__(16) float g_wfrag[COUT*CK];

__device__ __forceinline__ uint32_t f2tf32(float v) {
    uint32_t u;
    asm("cvt.rna.tf32.f32 %0, %1;" : "=r"(u) : "f"(v));
    return u;
}

// ------- transpose x: [B,C,HW] -> [B,HW,C], float4 both sides; wt fused on y==2 -------
__global__ void transpose_kernel(const float* __restrict__ x,
                                 const float* __restrict__ w) {
    __shared__ float tile[32][36];
    int b   = blockIdx.y;
    int tid = threadIdx.x;
    if (b == 2) {
        // weights: W[o][c][k] -> A-frag layout [mg(4)][ks(36)][lane(32)][slot(4)]
        int i = blockIdx.x*256 + tid;
        if (i < COUT*CK) {
            int s    = i & 3;
            int lane = (i >> 2) & 31;
            int ks   = (i >> 7) % NKS;
            int mg   = i / (NKS*128);
            int o  = mg*16 + (lane >> 2) + (s & 1)*8;
            int ck = ks*8 + (lane & 3) + (s >> 1)*4;
            int c = ck & 31, k = ck >> 5;
            g_wfrag[i] = __uint_as_float(f2tf32(w[(o*CIN + c)*KK + k]));
        }
        return;
    }
    int hw0 = blockIdx.x * 32;
    {
        int c = tid >> 3, q = tid & 7;
        float4 v = ((const float4*)x)[(((size_t)(b*CIN + c))*HWSZ + hw0)/4 + q];
        *(float4*)&tile[c][q*4] = v;
    }
    __syncthreads();
    {
        int hw = tid & 31, cq = tid >> 5;
        ((float4*)g_xt)[((size_t)b*HWSZ + hw0 + hw)*8 + cq] =
            make_float4(tile[cq*4+0][hw], tile[cq*4+1][hw],
                        tile[cq*4+2][hw], tile[cq*4+3][hw]);
    }
}

// ---------------- main: deep-pipelined gather + tf32 mma.sync, 4 CTAs/SM ----------------
__global__ void __launch_bounds__(NTHR, 4)
mapped_conv_kernel(const float* __restrict__ bias,
                   const float* __restrict__ smap,
                   float* __restrict__ out)
{
    __shared__ float  sB[2*NCOLS*SLW];     // 2304 fl, double-buffered sampled tile
    __shared__ int4   sIdx4[TPIX*KK];      // 144
    __shared__ float4 sWgt4[TPIX*KK];      // 144
    __shared__ float  sBias[COUT];

    const int tid  = threadIdx.x;
    const int w    = tid >> 5;             // 0..3
    const int lane = tid & 31;
    const int pix0 = blockIdx.x * TPIX;

    if (tid < COUT) sBias[tid] = bias[tid];

    // bilinear tables: task t = p*9+k, 144 tasks
    for (int t = tid; t < TPIX*KK; t += NTHR) {
        int p = t / KK, k = t - p*KK;
        float2 sxy = ((const float2*)smap)[(pix0 + p)*KK + k];
        float bx = floorf(sxy.x), by = floorf(sxy.y);
        float fx = sxy.x - bx,    fy = sxy.y - by;
        int x0 = (int)bx, y0 = (int)by;
        int x0c = min(max(x0, 0), WW-1);
        int x1c = min(x0 + 1, WW-1);
        int y0c = min(max(y0, 0), HH-1);
        int y1c = min(y0 + 1, HH-1);
        sIdx4[t] = make_int4(y0c*WW + x0c, y0c*WW + x1c,
                             y1c*WW + x0c, y1c*WW + x1c);
        sWgt4[t] = make_float4((1.f-fx)*(1.f-fy), fx*(1.f-fy),
                               (1.f-fx)*fy,       fx*fy);
    }

    // gather mapping: warp w -> 8 cols; col = b*16 + p
    const int gb_b  = w >> 1;
    const int gcol0 = w * 8;
    const int gp0   = (w & 1) * 8;
    const int cq    = lane & 7;
    const int cs    = lane >> 3;
    const float4* __restrict__ gxb4 = (const float4*)g_xt + (size_t)gb_b*HWSZ*8 + cq;

    // mma mapping: warp = mw (rows mw*16..+15), all 32 cols
    const int mw = w;
    const uint32_t* sBu = (const uint32_t*)sB;
    uint32_t bOff[4];
#pragma unroll
    for (int g = 0; g < 4; g++)
        bOff[g] = (uint32_t)(g*8 + (lane >> 2))*SLW + (lane & 3);

    const uint4* __restrict__ gw4 = (const uint4*)g_wfrag + (uint32_t)(mw*NKS)*32 + lane;

    float d[4][4];
#pragma unroll
    for (int g = 0; g < 4; g++)
#pragma unroll
        for (int j = 0; j < 4; j++) d[g][j] = 0.f;

    float4 vs[2][4];     // [col-iter][corner]
    uint4  Acur[4], Anx[4];

    __syncthreads();     // tables ready

    // ---- prologue: gather+store tap 0; issue tap 1 loads; prefetch A(0)
#pragma unroll
    for (int i = 0; i < 2; i++) {
        int p = gp0 + i*4 + cs;
        int4 id = sIdx4[p*KK];
        vs[i][0] = gxb4[(size_t)id.x*8];
        vs[i][1] = gxb4[(size_t)id.y*8];
        vs[i][2] = gxb4[(size_t)id.z*8];
        vs[i][3] = gxb4[(size_t)id.w*8];
    }
#pragma unroll
    for (int ksl = 0; ksl < 4; ksl++) Anx[ksl] = gw4[ksl*32];
#pragma unroll
    for (int i = 0; i < 2; i++) {
        int p   = gp0 + i*4 + cs;
        int col = gcol0 + i*4 + cs;
        float4 wt = sWgt4[p*KK];
        float ax = wt.x*vs[i][0].x + wt.y*vs[i][1].x + wt.z*vs[i][2].x + wt.w*vs[i][3].x;
        float ay = wt.x*vs[i][0].y + wt.y*vs[i][1].y + wt.z*vs[i][2].y + wt.w*vs[i][3].y;
        float az = wt.x*vs[i][0].z + wt.y*vs[i][1].z + wt.z*vs[i][2].z + wt.w*vs[i][3].z;
        float aw = wt.x*vs[i][0].w + wt.y*vs[i][1].w + wt.z*vs[i][2].w + wt.w*vs[i][3].w;
        *(float4*)&sB[(uint32_t)col*SLW + cq*4] =
            make_float4(__uint_as_float(f2tf32(ax)), __uint_as_float(f2tf32(ay)),
                        __uint_as_float(f2tf32(az)), __uint_as_float(f2tf32(aw)));
    }
    // issue tap-1 loads (land during first MMA)
#pragma unroll
    for (int i = 0; i < 2; i++) {
        int p = gp0 + i*4 + cs;
        int4 id = sIdx4[p*KK + 1];
        vs[i][0] = gxb4[(size_t)id.x*8];
        vs[i][1] = gxb4[(size_t)id.y*8];
        vs[i][2] = gxb4[(size_t)id.z*8];
        vs[i][3] = gxb4[(size_t)id.w*8];
    }
    __syncthreads();

    // ---- main loop: 9 taps, deep pipeline
#pragma unroll
    for (int k = 0; k < KK; k++) {
#pragma unroll
        for (int ksl = 0; ksl < 4; ksl++) Acur[ksl] = Anx[ksl];
        if (k + 1 < KK) {
#pragma unroll
            for (int ksl = 0; ksl < 4; ksl++) Anx[ksl] = gw4[((k+1)*4 + ksl)*32];
        }
        // MMA tap k (buf k&1)
        {
            const uint32_t bufb = (uint32_t)(k & 1) * (NCOLS*SLW);
#pragma unroll
            for (int ksl = 0; ksl < 4; ksl++) {
#pragma unroll
                for (int g = 0; g < 4; g++) {
                    uint32_t b0 = sBu[bufb + bOff[g] + ksl*8];
                    uint32_t b1 = sBu[bufb + bOff[g] + ksl*8 + 4];
                    asm volatile(
                        "mma.sync.aligned.m16n8k8.row.col.f32.tf32.tf32.f32 "
                        "{%0,%1,%2,%3}, {%4,%5,%6,%7}, {%8,%9}, {%0,%1,%2,%3};"
                        : "+f"(d[g][0]), "+f"(d[g][1]), "+f"(d[g][2]), "+f"(d[g][3])
                        : "r"(Acur[ksl].x), "r"(Acur[ksl].y),
                          "r"(Acur[ksl].z), "r"(Acur[ksl].w), "r"(b0), "r"(b1));
                }
            }
        }
        if (k + 1 < KK) {
            // combine tap k+1 (loads issued one full stage ago) + store
            float* dstb = sB + (uint32_t)((k + 1) & 1)*(NCOLS*SLW);
#pragma unroll
            for (int i = 0; i < 2; i++) {
                int p   = gp0 + i*4 + cs;
                int col = gcol0 + i*4 + cs;
                float4 wt = sWgt4[p*KK + k + 1];
                float ax = wt.x*vs[i][0].x + wt.y*vs[i][1].x + wt.z*vs[i][2].x + wt.w*vs[i][3].x;
                float ay = wt.x*vs[i][0].y + wt.y*vs[i][1].y + wt.z*vs[i][2].y + wt.w*vs[i][3].y;
                float az = wt.x*vs[i][0].z + wt.y*vs[i][1].z + wt.z*vs[i][2].z + wt.w*vs[i][3].z;
                float aw = wt.x*vs[i][0].w + wt.y*vs[i][1].w + wt.z*vs[i][2].w + wt.w*vs[i][3].w;
                *(float4*)&dstb[(uint32_t)col*SLW + cq*4] =
                    make_float4(__uint_as_float(f2tf32(ax)), __uint_as_float(f2tf32(ay)),
                                __uint_as_float(f2tf32(az)), __uint_as_float(f2tf32(aw)));
            }
            // issue tap k+2 loads into freed vs (in flight across sync + next MMA)
            if (k + 2 < KK) {
#pragma unroll
                for (int i = 0; i < 2; i++) {
                    int p = gp0 + i*4 + cs;
                    int4 id = sIdx4[p*KK + k + 2];
                    vs[i][0] = gxb4[(size_t)id.x*8];
                    vs[i][1] = gxb4[(size_t)id.y*8];
                    vs[i][2] = gxb4[(size_t)id.z*8];
                    vs[i][3] = gxb4[(size_t)id.w*8];
                }
            }
            __syncthreads();
        }
    }

    // ---- epilogue: D row = output channel o, col = (b, pixel)
    {
        int o0 = mw*16 + (lane >> 2);
        float bias0 = sBias[o0];
        float bias1 = sBias[o0 + 8];
#pragma unroll
        for (int g = 0; g < 4; g++) {
            int n  = g*8 + (lane & 3)*2;
            int bb = n >> 4;
            int p  = n & 15;
            float* op = out + ((size_t)(bb*COUT + o0))*OHW + pix0 + p;
            *(float2*)op = make_float2(d[g][0] + bias0, d[g][1] + bias0);
            *(float2*)(op + (size_t)8*OHW) = make_float2(d[g][2] + bias1, d[g][3] + bias1);
        }
    }
}

extern "C" void kernel_launch(void* const* d_in, const int* in_sizes, int n_in,
                              void* d_out, int out_size) {
    const float* x    = (const float*)d_in[0];
    const float* w    = (const float*)d_in[1];
    const float* bias = (const float*)d_in[2];
    const float* smap = (const float*)d_in[3];
    float* out = (float*)d_out;

    transpose_kernel<<<dim3(HWSZ/32, 3), 256>>>(x, w);   // y==2 slice does weights
    mapped_conv_kernel<<<OHW/TPIX, NTHR>>>(bias, smap, out);
}